// round 1
// baseline (speedup 1.0000x reference)
#include <cuda_runtime.h>

// Problem constants
#define BB 2
#define SSQ 2048
#define DDIM 2048
#define HH 16
#define HDH 128
#define M1 (BB * SSQ)      // 4096
#define N1 (3 * DDIM)      // 6144

// Scratch (allocation-free rule: __device__ globals)
__device__ float g_qkv[(size_t)M1 * N1];    // ~100 MB
__device__ float g_attn[(size_t)M1 * DDIM]; // ~33 MB

// ---------------------------------------------------------------------------
// SGEMM:  C[M,N] = A[M,K] * W[N,K]^T   (both A and W are K-major row-major)
// 64x64x16 tiles, 256 threads, 4x4 micro-tile per thread.
// ---------------------------------------------------------------------------
__global__ __launch_bounds__(256) void sgemm_nt(
    const float* __restrict__ A, const float* __restrict__ W,
    float* __restrict__ C, int M, int N, int K)
{
    __shared__ float As[16][65];
    __shared__ float Bs[16][65];

    const int t  = threadIdx.x;
    const int tx = t & 15;
    const int ty = t >> 4;
    const int bm = blockIdx.y << 6;
    const int bn = blockIdx.x << 6;
    const int lr = t >> 2;          // 0..63 tile row for loads
    const int lk = (t & 3) << 2;    // k quad

    const float* Ap = A + (size_t)(bm + lr) * K + lk;
    const float* Wp = W + (size_t)(bn + lr) * K + lk;

    float acc[4][4] = {};

    for (int k0 = 0; k0 < K; k0 += 16) {
        float4 av = *(const float4*)(Ap + k0);
        float4 wv = *(const float4*)(Wp + k0);
        As[lk + 0][lr] = av.x; As[lk + 1][lr] = av.y;
        As[lk + 2][lr] = av.z; As[lk + 3][lr] = av.w;
        Bs[lk + 0][lr] = wv.x; Bs[lk + 1][lr] = wv.y;
        Bs[lk + 2][lr] = wv.z; Bs[lk + 3][lr] = wv.w;
        __syncthreads();
#pragma unroll
        for (int k = 0; k < 16; k++) {
            float a0 = As[k][(ty << 2) + 0];
            float a1 = As[k][(ty << 2) + 1];
            float a2 = As[k][(ty << 2) + 2];
            float a3 = As[k][(ty << 2) + 3];
            float b0 = Bs[k][(tx << 2) + 0];
            float b1 = Bs[k][(tx << 2) + 1];
            float b2 = Bs[k][(tx << 2) + 2];
            float b3 = Bs[k][(tx << 2) + 3];
            acc[0][0] += a0 * b0; acc[0][1] += a0 * b1; acc[0][2] += a0 * b2; acc[0][3] += a0 * b3;
            acc[1][0] += a1 * b0; acc[1][1] += a1 * b1; acc[1][2] += a1 * b2; acc[1][3] += a1 * b3;
            acc[2][0] += a2 * b0; acc[2][1] += a2 * b1; acc[2][2] += a2 * b2; acc[2][3] += a2 * b3;
            acc[3][0] += a3 * b0; acc[3][1] += a3 * b1; acc[3][2] += a3 * b2; acc[3][3] += a3 * b3;
        }
        __syncthreads();
    }

#pragma unroll
    for (int j = 0; j < 4; j++) {
        float4 o = make_float4(acc[j][0], acc[j][1], acc[j][2], acc[j][3]);
        *(float4*)(C + (size_t)(bm + (ty << 2) + j) * N + bn + (tx << 2)) = o;
    }
}

// ---------------------------------------------------------------------------
// RoPE: applied in-place to q and k slices of g_qkv.
// One thread per (row, head, pair) handles q and k.
// ---------------------------------------------------------------------------
__global__ __launch_bounds__(256) void rope_kernel(
    const float* __restrict__ fc, const float* __restrict__ fs)
{
    int idx = blockIdx.x * blockDim.x + threadIdx.x;
    int i   = idx & 63;
    int h   = (idx >> 6) & 15;
    int row = idx >> 10;              // 0..4095 (= b*S + s)
    int s   = row & (SSQ - 1);

    float c  = fc[(s << 6) + i];
    float sn = fs[(s << 6) + i];

    float* pq = g_qkv + (size_t)row * N1 + (h << 7) + (i << 1);
    float2 q  = *(float2*)pq;
    *(float2*)pq = make_float2(q.x * c - q.y * sn, q.x * sn + q.y * c);

    float* pk = pq + DDIM;
    float2 kv = *(float2*)pk;
    *(float2*)pk = make_float2(kv.x * c - kv.y * sn, kv.x * sn + kv.y * c);
}

// ---------------------------------------------------------------------------
// Flash attention (fp32, causal). Block = 64 queries of one (b,h).
// Qs/Ks transposed [128][65] in smem; V natural [64][128]; Ss [64][65].
// 256 threads: score phase maps 16x16 (4x4 tile), softmax/PV phase maps
// (row = t/4, g = t&3) with interleaved float4 ownership of the 128 dims.
// ---------------------------------------------------------------------------
__global__ __launch_bounds__(256) void flash_kernel()
{
    extern __shared__ float sm[];
    float* Qs = sm;                 // [128][65]
    float* Ks = Qs + 128 * 65;      // [128][65]
    float* Vs = Ks + 128 * 65;      // [64][128]
    float* Ss = Vs + 64 * 128;      // [64][65]

    const int t  = threadIdx.x;
    const int qt = blockIdx.x;      // 0..31 query tile
    const int bh = blockIdx.y;      // 0..31
    const int b  = bh >> 4;
    const int h  = bh & 15;
    const int q0 = qt << 6;

    const int tx = t & 15, ty = t >> 4;   // score phase
    const int rr = t >> 2, g = t & 3;     // softmax / PV phase

    // Load Q tile (transposed into Qs[d][r])
    {
        const float* Qg = g_qkv + (size_t)(b * SSQ + q0) * N1 + (h << 7);
#pragma unroll
        for (int it = 0; it < 8; it++) {
            int flat = (it << 8) + t;
            int r_ = flat >> 5, d4 = flat & 31;
            float4 v = *(const float4*)(Qg + (size_t)r_ * N1 + (d4 << 2));
            Qs[(d4 * 4 + 0) * 65 + r_] = v.x;
            Qs[(d4 * 4 + 1) * 65 + r_] = v.y;
            Qs[(d4 * 4 + 2) * 65 + r_] = v.z;
            Qs[(d4 * 4 + 3) * 65 + r_] = v.w;
        }
    }

    float m = -1e30f, l = 0.0f;
    float4 acc[8];
#pragma unroll
    for (int u = 0; u < 8; u++) acc[u] = make_float4(0.f, 0.f, 0.f, 0.f);

    const float scale = 0.08838834764831845f;   // 1/sqrt(128)

    for (int kt = 0; kt <= qt; kt++) {
        __syncthreads();   // prev PV done (and Q store visible on first iter)

        // Load K (transposed) and V (natural)
        const float* Kg = g_qkv + (size_t)(b * SSQ + (kt << 6)) * N1 + DDIM + (h << 7);
        const float* Vg = Kg + DDIM;
#pragma unroll
        for (int it = 0; it < 8; it++) {
            int flat = (it << 8) + t;
            int r_ = flat >> 5, d4 = flat & 31;
            float4 kv = *(const float4*)(Kg + (size_t)r_ * N1 + (d4 << 2));
            Ks[(d4 * 4 + 0) * 65 + r_] = kv.x;
            Ks[(d4 * 4 + 1) * 65 + r_] = kv.y;
            Ks[(d4 * 4 + 2) * 65 + r_] = kv.z;
            Ks[(d4 * 4 + 3) * 65 + r_] = kv.w;
            float4 vv = *(const float4*)(Vg + (size_t)r_ * N1 + (d4 << 2));
            *(float4*)(Vs + r_ * 128 + (d4 << 2)) = vv;
        }
        __syncthreads();

        // Scores: S = Q @ K^T (64x64x128)
        float sc[4][4] = {};
#pragma unroll 4
        for (int k = 0; k < 128; k++) {
            const float* qrow = Qs + k * 65 + (ty << 2);
            const float* krow = Ks + k * 65 + (tx << 2);
            float a0 = qrow[0], a1 = qrow[1], a2 = qrow[2], a3 = qrow[3];
            float b0 = krow[0], b1 = krow[1], b2 = krow[2], b3 = krow[3];
            sc[0][0] += a0 * b0; sc[0][1] += a0 * b1; sc[0][2] += a0 * b2; sc[0][3] += a0 * b3;
            sc[1][0] += a1 * b0; sc[1][1] += a1 * b1; sc[1][2] += a1 * b2; sc[1][3] += a1 * b3;
            sc[2][0] += a2 * b0; sc[2][1] += a2 * b1; sc[2][2] += a2 * b2; sc[2][3] += a2 * b3;
            sc[3][0] += a3 * b0; sc[3][1] += a3 * b1; sc[3][2] += a3 * b2; sc[3][3] += a3 * b3;
        }
        const bool diag = (kt == qt);
#pragma unroll
        for (int j = 0; j < 4; j++) {
#pragma unroll
            for (int i2 = 0; i2 < 4; i2++) {
                float v = sc[j][i2] * scale;
                if (diag && ((tx << 2) + i2 > (ty << 2) + j)) v = -1e30f;
                Ss[((ty << 2) + j) * 65 + (tx << 2) + i2] = v;
            }
        }
        __syncwarp();   // Ss row is produced & consumed within the same warp

        // Online softmax (4 threads per row)
        float mloc = -1e30f;
#pragma unroll
        for (int c = 0; c < 16; c++)
            mloc = fmaxf(mloc, Ss[rr * 65 + (g << 4) + c]);
        mloc = fmaxf(mloc, __shfl_xor_sync(0xffffffff, mloc, 1));
        mloc = fmaxf(mloc, __shfl_xor_sync(0xffffffff, mloc, 2));
        float mnew  = fmaxf(m, mloc);
        float alpha = __expf(m - mnew);
        float ssum = 0.0f;
#pragma unroll
        for (int c = 0; c < 16; c++) {
            int ci = (g << 4) + c;
            float p = __expf(Ss[rr * 65 + ci] - mnew);
            Ss[rr * 65 + ci] = p;
            ssum += p;
        }
        ssum += __shfl_xor_sync(0xffffffff, ssum, 1);
        ssum += __shfl_xor_sync(0xffffffff, ssum, 2);
        l = l * alpha + ssum;
        m = mnew;
#pragma unroll
        for (int u = 0; u < 8; u++) {
            acc[u].x *= alpha; acc[u].y *= alpha;
            acc[u].z *= alpha; acc[u].w *= alpha;
        }
        __syncwarp();

        // PV accumulate: thread owns dims d = g*4 + dd*16 (+0..3)
#pragma unroll 2
        for (int c = 0; c < 64; c++) {
            float p = Ss[rr * 65 + c];
            const float* vrow = Vs + c * 128 + (g << 2);
#pragma unroll
            for (int dd = 0; dd < 8; dd++) {
                float4 v = *(const float4*)(vrow + (dd << 4));
                acc[dd].x += p * v.x; acc[dd].y += p * v.y;
                acc[dd].z += p * v.z; acc[dd].w += p * v.w;
            }
        }
    }

    // Final normalize + write to g_attn laid out [B,S,D]
    float inv = 1.0f / l;
    float* Og = g_attn + (size_t)(b * SSQ + q0 + rr) * DDIM + (h << 7) + (g << 2);
#pragma unroll
    for (int dd = 0; dd < 8; dd++) {
        float4 o = make_float4(acc[dd].x * inv, acc[dd].y * inv,
                               acc[dd].z * inv, acc[dd].w * inv);
        *(float4*)(Og + (dd << 4)) = o;
    }
}

// ---------------------------------------------------------------------------
// Launch
// ---------------------------------------------------------------------------
extern "C" void kernel_launch(void* const* d_in, const int* in_sizes, int n_in,
                              void* d_out, int out_size)
{
    const float* x     = (const float*)d_in[0];
    const float* wqkv  = (const float*)d_in[1];
    const float* wout  = (const float*)d_in[2];
    const float* fcos  = (const float*)d_in[3];
    const float* fsin  = (const float*)d_in[4];
    float* out = (float*)d_out;

    float *qkv_p = nullptr, *attn_p = nullptr;
    cudaGetSymbolAddress((void**)&qkv_p, g_qkv);
    cudaGetSymbolAddress((void**)&attn_p, g_attn);

    const int flash_smem = (128 * 65 + 128 * 65 + 64 * 128 + 64 * 65) * 4; // 115968 B
    cudaFuncSetAttribute(flash_kernel,
                         cudaFuncAttributeMaxDynamicSharedMemorySize, flash_smem);

    // 1) QKV projection: g_qkv = x @ w_qkv^T
    sgemm_nt<<<dim3(N1 / 64, M1 / 64), 256>>>(x, wqkv, qkv_p, M1, N1, DDIM);

    // 2) RoPE in place on q and k
    rope_kernel<<<(M1 * HH * 64) / 256, 256>>>(fcos, fsin);

    // 3) Causal flash attention -> g_attn
    flash_kernel<<<dim3(SSQ / 64, BB * HH), 256, flash_smem>>>();

    // 4) Output projection: out = g_attn @ w_out^T
    sgemm_nt<<<dim3(DDIM / 64, M1 / 64), 256>>>(attn_p, wout, out, M1, DDIM, DDIM);
}

// round 3
// speedup vs baseline: 1.8839x; 1.8839x over previous
#include <cuda_runtime.h>
#include <cuda_bf16.h>
#include <cstdint>

// Problem constants
#define BB 2
#define SSQ 2048
#define DDIM 2048
#define HH 16
#define M1 (BB * SSQ)      // 4096
#define N1 (3 * DDIM)      // 6144

// ---------------------------------------------------------------------------
// Scratch (__device__ globals: allocation-free rule)
// ---------------------------------------------------------------------------
__device__ float g_qkv[(size_t)M1 * N1];      // fp32 qkv
__device__ float g_attn[(size_t)M1 * DDIM];   // fp32 attention output
__device__ __nv_bfloat16 g_xhi[(size_t)M1 * DDIM];
__device__ __nv_bfloat16 g_xlo[(size_t)M1 * DDIM];
__device__ __nv_bfloat16 g_whi[(size_t)N1 * DDIM];
__device__ __nv_bfloat16 g_wlo[(size_t)N1 * DDIM];
__device__ __nv_bfloat16 g_ahi[(size_t)M1 * DDIM];
__device__ __nv_bfloat16 g_alo[(size_t)M1 * DDIM];
__device__ __nv_bfloat16 g_uhi[(size_t)DDIM * DDIM];
__device__ __nv_bfloat16 g_ulo[(size_t)DDIM * DDIM];

__device__ __forceinline__ uint32_t smem_u32(const void* p) {
    uint32_t a;
    asm("{ .reg .u64 t; cvta.to.shared.u64 t, %1; cvt.u32.u64 %0, t; }"
        : "=r"(a) : "l"(p));
    return a;
}

#define LDMX4(R, A) \
    asm volatile("ldmatrix.sync.aligned.m8n8.x4.shared.b16 {%0,%1,%2,%3}, [%4];" \
        : "=r"((R)[0]), "=r"((R)[1]), "=r"((R)[2]), "=r"((R)[3]) : "r"(A))

#define MMA_BF16(ac, a, b0v, b1v) \
    asm volatile("mma.sync.aligned.m16n8k16.row.col.f32.bf16.bf16.f32 " \
        "{%0,%1,%2,%3},{%4,%5,%6,%7},{%8,%9},{%0,%1,%2,%3};" \
        : "+f"((ac)[0]), "+f"((ac)[1]), "+f"((ac)[2]), "+f"((ac)[3]) \
        : "r"((a)[0]), "r"((a)[1]), "r"((a)[2]), "r"((a)[3]), \
          "r"(b0v), "r"(b1v))

#define CP_ASYNC16(s, g) \
    asm volatile("cp.async.cg.shared.global [%0], [%1], 16;" :: "r"(s), "l"(g))
#define CP_COMMIT() asm volatile("cp.async.commit_group;" ::: "memory")
#define CP_WAIT1()  asm volatile("cp.async.wait_group 1;" ::: "memory")
#define CP_WAIT0()  asm volatile("cp.async.wait_group 0;" ::: "memory")

// ---------------------------------------------------------------------------
// fp32 -> (bf16 hi, bf16 lo) split
// ---------------------------------------------------------------------------
__global__ __launch_bounds__(256) void split_bf16(
    const float* __restrict__ src, __nv_bfloat16* __restrict__ hi,
    __nv_bfloat16* __restrict__ lo, int n4)
{
    int i = blockIdx.x * blockDim.x + threadIdx.x;
    if (i >= n4) return;
    float4 v = ((const float4*)src)[i];
    __nv_bfloat16 h0 = __float2bfloat16(v.x);
    __nv_bfloat16 h1 = __float2bfloat16(v.y);
    __nv_bfloat16 h2 = __float2bfloat16(v.z);
    __nv_bfloat16 h3 = __float2bfloat16(v.w);
    __nv_bfloat16 l0 = __float2bfloat16(v.x - __bfloat162float(h0));
    __nv_bfloat16 l1 = __float2bfloat16(v.y - __bfloat162float(h1));
    __nv_bfloat16 l2 = __float2bfloat16(v.z - __bfloat162float(h2));
    __nv_bfloat16 l3 = __float2bfloat16(v.w - __bfloat162float(h3));
    ((__nv_bfloat162*)hi)[i * 2 + 0] = __nv_bfloat162(h0, h1);
    ((__nv_bfloat162*)hi)[i * 2 + 1] = __nv_bfloat162(h2, h3);
    ((__nv_bfloat162*)lo)[i * 2 + 0] = __nv_bfloat162(l0, l1);
    ((__nv_bfloat162*)lo)[i * 2 + 1] = __nv_bfloat162(l2, l3);
}

// ---------------------------------------------------------------------------
// mma.sync GEMM:  C[M,N] = A[M,K] * W[N,K]^T  with 3-term bf16 split.
// CTA 128x128, warp 64x32, K-chunk 32, cp.async double buffering.
// Smem rows padded to 40 bf16 (80B) -> conflict-free ldmatrix.
// ---------------------------------------------------------------------------
#define KC 32
#define AST 40                      // padded row stride (bf16 elems)
#define TILE_E (128 * AST)          // elems per tile (one matrix term)
#define STAGE_E (4 * TILE_E)        // Ahi,Alo,Bhi,Blo
#define GEMM_SMEM (2 * STAGE_E * 2) // bytes = 81920

__global__ __launch_bounds__(256, 1) void mma_gemm(
    const __nv_bfloat16* __restrict__ Ahi, const __nv_bfloat16* __restrict__ Alo,
    const __nv_bfloat16* __restrict__ Bhi, const __nv_bfloat16* __restrict__ Blo,
    float* __restrict__ C, int Ntot, int K)
{
    extern __shared__ __nv_bfloat16 smb[];
    const uint32_t sbase = smem_u32(smb);
    const int t = threadIdx.x;
    const int lane = t & 31, warp = t >> 5;
    const int bm = blockIdx.y << 7, bn = blockIdx.x << 7;
    const int wm = (warp >> 2) << 6;   // 0 / 64
    const int wn = (warp & 3) << 5;    // 0,32,64,96

    // loader mapping: thread t -> row lr, 16B chunks lc0, lc0+1
    const int lr = t >> 1;
    const int lc0 = (t & 1) << 1;

    const __nv_bfloat16* gsrc[4] = {
        Ahi + (size_t)(bm + lr) * K, Alo + (size_t)(bm + lr) * K,
        Bhi + (size_t)(bn + lr) * K, Blo + (size_t)(bn + lr) * K };

    auto load_stage = [&](int kc, int buf) {
        uint32_t sb = sbase + buf * STAGE_E * 2;
#pragma unroll
        for (int tile = 0; tile < 4; tile++) {
#pragma unroll
            for (int i = 0; i < 2; i++) {
                int c = lc0 + i;
                uint32_t sa = sb + tile * TILE_E * 2 + (lr * AST + c * 8) * 2;
                const void* ga = gsrc[tile] + kc * KC + c * 8;
                CP_ASYNC16(sa, ga);
            }
        }
        CP_COMMIT();
    };

    float acc[4][4][4] = {};
    const int NIT = K / KC;

    load_stage(0, 0);

    const int ldrow = lane & 15;
    const int ldcol = (lane >> 4) << 3;

    for (int it = 0; it < NIT; it++) {
        if (it + 1 < NIT) { load_stage(it + 1, (it + 1) & 1); CP_WAIT1(); }
        else              { CP_WAIT0(); }
        __syncthreads();

        const uint32_t sb = sbase + (it & 1) * STAGE_E * 2;
#pragma unroll
        for (int kh = 0; kh < 2; kh++) {
            uint32_t aH[4][4], aL[4][4], bH[4][2], bL[4][2];
            const int colb = (kh * 16 + ldcol) * 2;
#pragma unroll
            for (int mt = 0; mt < 4; mt++) {
                uint32_t ra = sb + (wm + mt * 16 + ldrow) * (AST * 2) + colb;
                LDMX4(aH[mt], ra);
                LDMX4(aL[mt], ra + TILE_E * 2);
            }
#pragma unroll
            for (int n2 = 0; n2 < 2; n2++) {
                uint32_t rb = sb + 2 * TILE_E * 2 +
                              (wn + n2 * 16 + ldrow) * (AST * 2) + colb;
                uint32_t r[4];
                LDMX4(r, rb);
                bH[n2 * 2 + 0][0] = r[0]; bH[n2 * 2 + 0][1] = r[2];
                bH[n2 * 2 + 1][0] = r[1]; bH[n2 * 2 + 1][1] = r[3];
                LDMX4(r, rb + TILE_E * 2);
                bL[n2 * 2 + 0][0] = r[0]; bL[n2 * 2 + 0][1] = r[2];
                bL[n2 * 2 + 1][0] = r[1]; bL[n2 * 2 + 1][1] = r[3];
            }
#pragma unroll
            for (int mt = 0; mt < 4; mt++) {
#pragma unroll
                for (int nt = 0; nt < 4; nt++) {
                    MMA_BF16(acc[mt][nt], aH[mt], bH[nt][0], bH[nt][1]);
                    MMA_BF16(acc[mt][nt], aH[mt], bL[nt][0], bL[nt][1]);
                    MMA_BF16(acc[mt][nt], aL[mt], bH[nt][0], bH[nt][1]);
                }
            }
        }
        __syncthreads();
    }

    // epilogue
    const int grp = lane >> 2, q = (lane & 3) << 1;
#pragma unroll
    for (int mt = 0; mt < 4; mt++) {
#pragma unroll
        for (int nt = 0; nt < 4; nt++) {
            float* p = C + (size_t)(bm + wm + mt * 16 + grp) * Ntot
                         + bn + wn + nt * 8 + q;
            p[0] = acc[mt][nt][0];
            p[1] = acc[mt][nt][1];
            float* p2 = p + (size_t)8 * Ntot;
            p2[0] = acc[mt][nt][2];
            p2[1] = acc[mt][nt][3];
        }
    }
}

// ---------------------------------------------------------------------------
// RoPE (in place on q,k slices of g_qkv)
// ---------------------------------------------------------------------------
__global__ __launch_bounds__(256) void rope_kernel(
    const float* __restrict__ fc, const float* __restrict__ fs)
{
    int idx = blockIdx.x * blockDim.x + threadIdx.x;
    int i   = idx & 63;
    int h   = (idx >> 6) & 15;
    int row = idx >> 10;
    int s   = row & (SSQ - 1);

    float c  = fc[(s << 6) + i];
    float sn = fs[(s << 6) + i];

    float* pq = g_qkv + (size_t)row * N1 + (h << 7) + (i << 1);
    float2 q  = *(float2*)pq;
    *(float2*)pq = make_float2(q.x * c - q.y * sn, q.x * sn + q.y * c);

    float* pk = pq + DDIM;
    float2 kv = *(float2*)pk;
    *(float2*)pk = make_float2(kv.x * c - kv.y * sn, kv.x * sn + kv.y * c);
}

// ---------------------------------------------------------------------------
// Flash attention (fp32, causal) — unchanged (known good)
// ---------------------------------------------------------------------------
__global__ __launch_bounds__(256) void flash_kernel()
{
    extern __shared__ float sm[];
    float* Qs = sm;                 // [128][65]
    float* Ks = Qs + 128 * 65;      // [128][65]
    float* Vs = Ks + 128 * 65;      // [64][128]
    float* Ss = Vs + 64 * 128;      // [64][65]

    const int t  = threadIdx.x;
    const int qt = blockIdx.x;
    const int bh = blockIdx.y;
    const int b  = bh >> 4;
    const int h  = bh & 15;
    const int q0 = qt << 6;

    const int tx = t & 15, ty = t >> 4;
    const int rr = t >> 2, g = t & 3;

    {
        const float* Qg = g_qkv + (size_t)(b * SSQ + q0) * N1 + (h << 7);
#pragma unroll
        for (int it = 0; it < 8; it++) {
            int flat = (it << 8) + t;
            int r_ = flat >> 5, d4 = flat & 31;
            float4 v = *(const float4*)(Qg + (size_t)r_ * N1 + (d4 << 2));
            Qs[(d4 * 4 + 0) * 65 + r_] = v.x;
            Qs[(d4 * 4 + 1) * 65 + r_] = v.y;
            Qs[(d4 * 4 + 2) * 65 + r_] = v.z;
            Qs[(d4 * 4 + 3) * 65 + r_] = v.w;
        }
    }

    float m = -1e30f, l = 0.0f;
    float4 acc[8];
#pragma unroll
    for (int u = 0; u < 8; u++) acc[u] = make_float4(0.f, 0.f, 0.f, 0.f);

    const float scale = 0.08838834764831845f;

    for (int kt = 0; kt <= qt; kt++) {
        __syncthreads();

        const float* Kg = g_qkv + (size_t)(b * SSQ + (kt << 6)) * N1 + DDIM + (h << 7);
        const float* Vg = Kg + DDIM;
#pragma unroll
        for (int it = 0; it < 8; it++) {
            int flat = (it << 8) + t;
            int r_ = flat >> 5, d4 = flat & 31;
            float4 kv = *(const float4*)(Kg + (size_t)r_ * N1 + (d4 << 2));
            Ks[(d4 * 4 + 0) * 65 + r_] = kv.x;
            Ks[(d4 * 4 + 1) * 65 + r_] = kv.y;
            Ks[(d4 * 4 + 2) * 65 + r_] = kv.z;
            Ks[(d4 * 4 + 3) * 65 + r_] = kv.w;
            float4 vv = *(const float4*)(Vg + (size_t)r_ * N1 + (d4 << 2));
            *(float4*)(Vs + r_ * 128 + (d4 << 2)) = vv;
        }
        __syncthreads();

        float sc[4][4] = {};
#pragma unroll 4
        for (int k = 0; k < 128; k++) {
            const float* qrow = Qs + k * 65 + (ty << 2);
            const float* krow = Ks + k * 65 + (tx << 2);
            float a0 = qrow[0], a1 = qrow[1], a2 = qrow[2], a3 = qrow[3];
            float b0 = krow[0], b1 = krow[1], b2 = krow[2], b3 = krow[3];
            sc[0][0] += a0 * b0; sc[0][1] += a0 * b1; sc[0][2] += a0 * b2; sc[0][3] += a0 * b3;
            sc[1][0] += a1 * b0; sc[1][1] += a1 * b1; sc[1][2] += a1 * b2; sc[1][3] += a1 * b3;
            sc[2][0] += a2 * b0; sc[2][1] += a2 * b1; sc[2][2] += a2 * b2; sc[2][3] += a2 * b3;
            sc[3][0] += a3 * b0; sc[3][1] += a3 * b1; sc[3][2] += a3 * b2; sc[3][3] += a3 * b3;
        }
        const bool diag = (kt == qt);
#pragma unroll
        for (int j = 0; j < 4; j++) {
#pragma unroll
            for (int i2 = 0; i2 < 4; i2++) {
                float v = sc[j][i2] * scale;
                if (diag && ((tx << 2) + i2 > (ty << 2) + j)) v = -1e30f;
                Ss[((ty << 2) + j) * 65 + (tx << 2) + i2] = v;
            }
        }
        __syncwarp();

        float mloc = -1e30f;
#pragma unroll
        for (int c = 0; c < 16; c++)
            mloc = fmaxf(mloc, Ss[rr * 65 + (g << 4) + c]);
        mloc = fmaxf(mloc, __shfl_xor_sync(0xffffffff, mloc, 1));
        mloc = fmaxf(mloc, __shfl_xor_sync(0xffffffff, mloc, 2));
        float mnew  = fmaxf(m, mloc);
        float alpha = __expf(m - mnew);
        float ssum = 0.0f;
#pragma unroll
        for (int c = 0; c < 16; c++) {
            int ci = (g << 4) + c;
            float p = __expf(Ss[rr * 65 + ci] - mnew);
            Ss[rr * 65 + ci] = p;
            ssum += p;
        }
        ssum += __shfl_xor_sync(0xffffffff, ssum, 1);
        ssum += __shfl_xor_sync(0xffffffff, ssum, 2);
        l = l * alpha + ssum;
        m = mnew;
#pragma unroll
        for (int u = 0; u < 8; u++) {
            acc[u].x *= alpha; acc[u].y *= alpha;
            acc[u].z *= alpha; acc[u].w *= alpha;
        }
        __syncwarp();

#pragma unroll 2
        for (int c = 0; c < 64; c++) {
            float p = Ss[rr * 65 + c];
            const float* vrow = Vs + c * 128 + (g << 2);
#pragma unroll
            for (int dd = 0; dd < 8; dd++) {
                float4 v = *(const float4*)(vrow + (dd << 4));
                acc[dd].x += p * v.x; acc[dd].y += p * v.y;
                acc[dd].z += p * v.z; acc[dd].w += p * v.w;
            }
        }
    }

    float inv = 1.0f / l;
    float* Og = g_attn + (size_t)(b * SSQ + q0 + rr) * DDIM + (h << 7) + (g << 2);
#pragma unroll
    for (int dd = 0; dd < 8; dd++) {
        float4 o = make_float4(acc[dd].x * inv, acc[dd].y * inv,
                               acc[dd].z * inv, acc[dd].w * inv);
        *(float4*)(Og + (dd << 4)) = o;
    }
}

// ---------------------------------------------------------------------------
// Launch
// ---------------------------------------------------------------------------
extern "C" void kernel_launch(void* const* d_in, const int* in_sizes, int n_in,
                              void* d_out, int out_size)
{
    const float* x     = (const float*)d_in[0];
    const float* wqkv  = (const float*)d_in[1];
    const float* wout  = (const float*)d_in[2];
    const float* fcos  = (const float*)d_in[3];
    const float* fsin  = (const float*)d_in[4];
    float* out = (float*)d_out;

    float *qkv_p = nullptr, *attn_p = nullptr;
    __nv_bfloat16 *xhi, *xlo, *whi, *wlo, *ahi, *alo, *uhi, *ulo;
    cudaGetSymbolAddress((void**)&qkv_p, g_qkv);
    cudaGetSymbolAddress((void**)&attn_p, g_attn);
    cudaGetSymbolAddress((void**)&xhi, g_xhi);
    cudaGetSymbolAddress((void**)&xlo, g_xlo);
    cudaGetSymbolAddress((void**)&whi, g_whi);
    cudaGetSymbolAddress((void**)&wlo, g_wlo);
    cudaGetSymbolAddress((void**)&ahi, g_ahi);
    cudaGetSymbolAddress((void**)&alo, g_alo);
    cudaGetSymbolAddress((void**)&uhi, g_uhi);
    cudaGetSymbolAddress((void**)&ulo, g_ulo);

    cudaFuncSetAttribute(mma_gemm, cudaFuncAttributeMaxDynamicSharedMemorySize,
                         GEMM_SMEM);
    const int flash_smem = (128 * 65 + 128 * 65 + 64 * 128 + 64 * 65) * 4;
    cudaFuncSetAttribute(flash_kernel,
                         cudaFuncAttributeMaxDynamicSharedMemorySize, flash_smem);

    // splits
    split_bf16<<<(M1 * DDIM / 4) / 256, 256>>>(x, xhi, xlo, M1 * DDIM / 4);
    split_bf16<<<(N1 * DDIM / 4) / 256, 256>>>(wqkv, whi, wlo, N1 * DDIM / 4);
    split_bf16<<<(DDIM * DDIM / 4) / 256, 256>>>(wout, uhi, ulo, DDIM * DDIM / 4);

    // 1) QKV projection on tensor cores (mma.sync)
    mma_gemm<<<dim3(N1 / 128, M1 / 128), 256, GEMM_SMEM>>>(
        xhi, xlo, whi, wlo, qkv_p, N1, DDIM);

    // 2) RoPE
    rope_kernel<<<(M1 * HH * 64) / 256, 256>>>(fcos, fsin);

    // 3) Flash attention
    flash_kernel<<<dim3(SSQ / 64, BB * HH), 256, flash_smem>>>();

    // 4) split attention output, then output projection
    split_bf16<<<(M1 * DDIM / 4) / 256, 256>>>(attn_p, ahi, alo, M1 * DDIM / 4);
    mma_gemm<<<dim3(DDIM / 128, M1 / 128), 256, GEMM_SMEM>>>(
        ahi, alo, uhi, ulo, out, DDIM, DDIM);
}

// round 4
// speedup vs baseline: 3.3410x; 1.7734x over previous
#include <cuda_runtime.h>
#include <cuda_bf16.h>
#include <cstdint>

// Problem constants
#define BB 2
#define SSQ 2048
#define DDIM 2048
#define HH 16
#define M1 (BB * SSQ)      // 4096
#define N1 (3 * DDIM)      // 6144
#define FB (BB * HH)       // 32 (b,h) pairs

// ---------------------------------------------------------------------------
// Scratch (__device__ globals: allocation-free rule)
// ---------------------------------------------------------------------------
__device__ float g_qkv[(size_t)M1 * N1];      // fp32 qkv (GEMM1 out)
__device__ __nv_bfloat16 g_xhi[(size_t)M1 * DDIM];
__device__ __nv_bfloat16 g_xlo[(size_t)M1 * DDIM];
__device__ __nv_bfloat16 g_whi[(size_t)N1 * DDIM];
__device__ __nv_bfloat16 g_wlo[(size_t)N1 * DDIM];
__device__ __nv_bfloat16 g_ahi[(size_t)M1 * DDIM];
__device__ __nv_bfloat16 g_alo[(size_t)M1 * DDIM];
__device__ __nv_bfloat16 g_uhi[(size_t)DDIM * DDIM];
__device__ __nv_bfloat16 g_ulo[(size_t)DDIM * DDIM];
// flash operands, layout [bh][s][128], bf16 hi/lo
__device__ __nv_bfloat16 g_qhi[(size_t)FB * SSQ * 128];
__device__ __nv_bfloat16 g_qlo[(size_t)FB * SSQ * 128];
__device__ __nv_bfloat16 g_khi[(size_t)FB * SSQ * 128];
__device__ __nv_bfloat16 g_klo[(size_t)FB * SSQ * 128];
__device__ __nv_bfloat16 g_vhi[(size_t)FB * SSQ * 128];
__device__ __nv_bfloat16 g_vlo[(size_t)FB * SSQ * 128];

__device__ __forceinline__ uint32_t smem_u32(const void* p) {
    uint32_t a;
    asm("{ .reg .u64 t; cvta.to.shared.u64 t, %1; cvt.u32.u64 %0, t; }"
        : "=r"(a) : "l"(p));
    return a;
}

#define LDMX4(R, A) \
    asm volatile("ldmatrix.sync.aligned.m8n8.x4.shared.b16 {%0,%1,%2,%3}, [%4];" \
        : "=r"((R)[0]), "=r"((R)[1]), "=r"((R)[2]), "=r"((R)[3]) : "r"(A))
#define LDMX4T(R, A) \
    asm volatile("ldmatrix.sync.aligned.m8n8.x4.trans.shared.b16 {%0,%1,%2,%3}, [%4];" \
        : "=r"((R)[0]), "=r"((R)[1]), "=r"((R)[2]), "=r"((R)[3]) : "r"(A))

#define MMA_BF16(ac, a, b0v, b1v) \
    asm volatile("mma.sync.aligned.m16n8k16.row.col.f32.bf16.bf16.f32 " \
        "{%0,%1,%2,%3},{%4,%5,%6,%7},{%8,%9},{%0,%1,%2,%3};" \
        : "+f"((ac)[0]), "+f"((ac)[1]), "+f"((ac)[2]), "+f"((ac)[3]) \
        : "r"((a)[0]), "r"((a)[1]), "r"((a)[2]), "r"((a)[3]), \
          "r"(b0v), "r"(b1v))

#define CP_ASYNC16(s, g) \
    asm volatile("cp.async.cg.shared.global [%0], [%1], 16;" :: "r"(s), "l"(g))
#define CP_COMMIT() asm volatile("cp.async.commit_group;" ::: "memory")
#define CP_WAIT1()  asm volatile("cp.async.wait_group 1;" ::: "memory")
#define CP_WAIT0()  asm volatile("cp.async.wait_group 0;" ::: "memory")

// split fp32 pair -> packed bf16x2 (hi) + packed bf16x2 (lo residual)
__device__ __forceinline__ void split_pack(float x, float y,
                                           uint32_t& hi, uint32_t& lo) {
    __nv_bfloat162 h = __floats2bfloat162_rn(x, y);
    hi = *reinterpret_cast<uint32_t*>(&h);
    __nv_bfloat162 l = __floats2bfloat162_rn(x - __low2float(h),
                                             y - __high2float(h));
    lo = *reinterpret_cast<uint32_t*>(&l);
}

// ---------------------------------------------------------------------------
// fp32 -> (bf16 hi, bf16 lo) split (for GEMM operands)
// ---------------------------------------------------------------------------
__global__ __launch_bounds__(256) void split_bf16(
    const float* __restrict__ src, __nv_bfloat16* __restrict__ hi,
    __nv_bfloat16* __restrict__ lo, int n4)
{
    int i = blockIdx.x * blockDim.x + threadIdx.x;
    if (i >= n4) return;
    float4 v = ((const float4*)src)[i];
    uint32_t h0, l0, h1, l1;
    split_pack(v.x, v.y, h0, l0);
    split_pack(v.z, v.w, h1, l1);
    ((uint32_t*)hi)[i * 2 + 0] = h0;
    ((uint32_t*)hi)[i * 2 + 1] = h1;
    ((uint32_t*)lo)[i * 2 + 0] = l0;
    ((uint32_t*)lo)[i * 2 + 1] = l1;
}

// ---------------------------------------------------------------------------
// mma.sync GEMM (unchanged from passing round)
// ---------------------------------------------------------------------------
#define KC 32
#define AST 40
#define TILE_E (128 * AST)
#define STAGE_E (4 * TILE_E)
#define GEMM_SMEM (2 * STAGE_E * 2)

__global__ __launch_bounds__(256, 1) void mma_gemm(
    const __nv_bfloat16* __restrict__ Ahi, const __nv_bfloat16* __restrict__ Alo,
    const __nv_bfloat16* __restrict__ Bhi, const __nv_bfloat16* __restrict__ Blo,
    float* __restrict__ C, int Ntot, int K)
{
    extern __shared__ __nv_bfloat16 smb[];
    const uint32_t sbase = smem_u32(smb);
    const int t = threadIdx.x;
    const int lane = t & 31, warp = t >> 5;
    const int bm = blockIdx.y << 7, bn = blockIdx.x << 7;
    const int wm = (warp >> 2) << 6;
    const int wn = (warp & 3) << 5;

    const int lr = t >> 1;
    const int lc0 = (t & 1) << 1;

    const __nv_bfloat16* gsrc[4] = {
        Ahi + (size_t)(bm + lr) * K, Alo + (size_t)(bm + lr) * K,
        Bhi + (size_t)(bn + lr) * K, Blo + (size_t)(bn + lr) * K };

    auto load_stage = [&](int kc, int buf) {
        uint32_t sb = sbase + buf * STAGE_E * 2;
#pragma unroll
        for (int tile = 0; tile < 4; tile++) {
#pragma unroll
            for (int i = 0; i < 2; i++) {
                int c = lc0 + i;
                uint32_t sa = sb + tile * TILE_E * 2 + (lr * AST + c * 8) * 2;
                const void* ga = gsrc[tile] + kc * KC + c * 8;
                CP_ASYNC16(sa, ga);
            }
        }
        CP_COMMIT();
    };

    float acc[4][4][4] = {};
    const int NIT = K / KC;

    load_stage(0, 0);

    const int ldrow = lane & 15;
    const int ldcol = (lane >> 4) << 3;

    for (int it = 0; it < NIT; it++) {
        if (it + 1 < NIT) { load_stage(it + 1, (it + 1) & 1); CP_WAIT1(); }
        else              { CP_WAIT0(); }
        __syncthreads();

        const uint32_t sb = sbase + (it & 1) * STAGE_E * 2;
#pragma unroll
        for (int kh = 0; kh < 2; kh++) {
            uint32_t aH[4][4], aL[4][4], bH[4][2], bL[4][2];
            const int colb = (kh * 16 + ldcol) * 2;
#pragma unroll
            for (int mt = 0; mt < 4; mt++) {
                uint32_t ra = sb + (wm + mt * 16 + ldrow) * (AST * 2) + colb;
                LDMX4(aH[mt], ra);
                LDMX4(aL[mt], ra + TILE_E * 2);
            }
#pragma unroll
            for (int n2 = 0; n2 < 2; n2++) {
                uint32_t rb = sb + 2 * TILE_E * 2 +
                              (wn + n2 * 16 + ldrow) * (AST * 2) + colb;
                uint32_t r[4];
                LDMX4(r, rb);
                bH[n2 * 2 + 0][0] = r[0]; bH[n2 * 2 + 0][1] = r[2];
                bH[n2 * 2 + 1][0] = r[1]; bH[n2 * 2 + 1][1] = r[3];
                LDMX4(r, rb + TILE_E * 2);
                bL[n2 * 2 + 0][0] = r[0]; bL[n2 * 2 + 0][1] = r[2];
                bL[n2 * 2 + 1][0] = r[1]; bL[n2 * 2 + 1][1] = r[3];
            }
#pragma unroll
            for (int mt = 0; mt < 4; mt++) {
#pragma unroll
                for (int nt = 0; nt < 4; nt++) {
                    MMA_BF16(acc[mt][nt], aH[mt], bH[nt][0], bH[nt][1]);
                    MMA_BF16(acc[mt][nt], aH[mt], bL[nt][0], bL[nt][1]);
                    MMA_BF16(acc[mt][nt], aL[mt], bH[nt][0], bH[nt][1]);
                }
            }
        }
        __syncthreads();
    }

    const int grp = lane >> 2, q = (lane & 3) << 1;
#pragma unroll
    for (int mt = 0; mt < 4; mt++) {
#pragma unroll
        for (int nt = 0; nt < 4; nt++) {
            float* p = C + (size_t)(bm + wm + mt * 16 + grp) * Ntot
                         + bn + wn + nt * 8 + q;
            p[0] = acc[mt][nt][0];
            p[1] = acc[mt][nt][1];
            float* p2 = p + (size_t)8 * Ntot;
            p2[0] = acc[mt][nt][2];
            p2[1] = acc[mt][nt][3];
        }
    }
}

// ---------------------------------------------------------------------------
// RoPE + relayout + bf16 split:
// reads fp32 q,k,v from g_qkv, applies rope to q,k (q pre-scaled by 1/sqrt(HD)),
// writes bf16 hi/lo into [bh][s][128] arrays.
// ---------------------------------------------------------------------------
__global__ __launch_bounds__(256) void rope_split_kernel(
    const float* __restrict__ fc, const float* __restrict__ fs)
{
    int idx = blockIdx.x * blockDim.x + threadIdx.x; // over B*S*H*64
    int i   = idx & 63;
    int h   = (idx >> 6) & 15;
    int sb  = idx >> 10;               // b*S + s
    int s   = sb & (SSQ - 1);
    int b   = sb >> 11;

    float c  = fc[(s << 6) + i];
    float sn = fs[(s << 6) + i];

    const float* base = g_qkv + (size_t)sb * N1 + (h << 7) + (i << 1);
    float2 q = *(const float2*)base;
    float2 k = *(const float2*)(base + DDIM);
    float2 v = *(const float2*)(base + 2 * DDIM);

    const float scale = 0.08838834764831845f; // 1/sqrt(128), folded into q
    float qx = (q.x * c - q.y * sn) * scale;
    float qy = (q.x * sn + q.y * c) * scale;
    float kx = k.x * c - k.y * sn;
    float ky = k.x * sn + k.y * c;

    size_t o = ((size_t)(b * HH + h) * SSQ + s) * 128 + (i << 1);
    uint32_t hi, lo;
    split_pack(qx, qy, hi, lo);
    *(uint32_t*)(g_qhi + o) = hi;  *(uint32_t*)(g_qlo + o) = lo;
    split_pack(kx, ky, hi, lo);
    *(uint32_t*)(g_khi + o) = hi;  *(uint32_t*)(g_klo + o) = lo;
    split_pack(v.x, v.y, hi, lo);
    *(uint32_t*)(g_vhi + o) = hi;  *(uint32_t*)(g_vlo + o) = lo;
}

// ---------------------------------------------------------------------------
// Flash attention on mma.sync (bf16 3-term split, fp32 softmax).
// Q tile 128, K tile 64, 8 warps (warp owns 16 q rows), cp.async double buffer.
// Writes bf16 hi/lo output directly (input to GEMM2).
// ---------------------------------------------------------------------------
#define FSTR 136                    // padded row stride (bf16 elems)
#define FTILE (64 * FSTR)           // one K/V tile (elems)
#define QTILE (128 * FSTR)          // one Q tile (elems)
#define FLASH_SMEM ((2 * QTILE + 8 * FTILE) * 2)   // 208896 bytes

__global__ __launch_bounds__(256, 1) void flash_mma(
    const __nv_bfloat16* __restrict__ qhi, const __nv_bfloat16* __restrict__ qlo,
    const __nv_bfloat16* __restrict__ khi, const __nv_bfloat16* __restrict__ klo,
    const __nv_bfloat16* __restrict__ vhi, const __nv_bfloat16* __restrict__ vlo,
    __nv_bfloat16* __restrict__ ohi, __nv_bfloat16* __restrict__ olo)
{
    extern __shared__ __nv_bfloat16 fsm[];
    const uint32_t sb = smem_u32(fsm);
    const int t = threadIdx.x;
    const int lane = t & 31, warp = t >> 5;
    const int qt = (int)gridDim.x - 1 - (int)blockIdx.x;  // long work first
    const int bh = blockIdx.y;
    const int q0 = qt << 7;
    const size_t bhbase = (size_t)bh * SSQ * 128;

    const int ldr = lane & 15;
    const int ldc = (lane >> 4) << 3;
    const int grp = lane >> 2;
    const int qq  = (lane & 3) << 1;

    // ---- stage Q (hi,lo) via cp.async
    {
        int r = t >> 1;
        int e0 = (t & 1) << 6;   // elem offset 0 or 64
        const __nv_bfloat16* srcs[2] = {
            qhi + bhbase + (size_t)(q0 + r) * 128 + e0,
            qlo + bhbase + (size_t)(q0 + r) * 128 + e0 };
        uint32_t s0 = sb + (r * FSTR + e0) * 2;
#pragma unroll
        for (int tile = 0; tile < 2; tile++)
#pragma unroll
            for (int c = 0; c < 8; c++)
                CP_ASYNC16(s0 + tile * QTILE * 2 + c * 16, srcs[tile] + c * 8);
        CP_COMMIT();
    }

    // KV stage loader
    auto load_kv = [&](int kt, int buf) {
        int r = t >> 2;
        int e0 = (t & 3) << 5;   // elem offset: 0,32,64,96
        size_t g0 = bhbase + (size_t)(kt * 64 + r) * 128 + e0;
        const __nv_bfloat16* srcs[4] = { khi + g0, klo + g0, vhi + g0, vlo + g0 };
        uint32_t s0 = sb + (2 * QTILE + buf * 4 * FTILE + r * FSTR + e0) * 2;
#pragma unroll
        for (int tile = 0; tile < 4; tile++)
#pragma unroll
            for (int c = 0; c < 4; c++)
                CP_ASYNC16(s0 + tile * FTILE * 2 + c * 16, srcs[tile] + c * 8);
        CP_COMMIT();
    };

    // ---- Q fragments (persistent)
    CP_WAIT0();
    __syncthreads();
    uint32_t qh[8][4], ql[8][4];
    const int wrow = warp << 4;
#pragma unroll
    for (int d = 0; d < 8; d++) {
        uint32_t a = sb + ((wrow + ldr) * FSTR + d * 16 + ldc) * 2;
        LDMX4(qh[d], a);
        LDMX4(ql[d], a + QTILE * 2);
    }

    const int ktmax = 2 * qt + 1;
    load_kv(0, 0);
    load_kv(1, 1);

    float Of[16][4] = {};
    float m0 = -1e30f, m1 = -1e30f, l0 = 0.f, l1 = 0.f;

    for (int kt = 0; kt <= ktmax; kt++) {
        if (kt == ktmax) { CP_WAIT0(); } else { CP_WAIT1(); }
        __syncthreads();

        const uint32_t kvb = sb + (2 * QTILE + (kt & 1) * 4 * FTILE) * 2;

        // ---- S = Q K^T  (16 x 64 per warp)
        float Sf[8][4] = {};
#pragma unroll
        for (int d = 0; d < 8; d++) {
#pragma unroll
            for (int n4 = 0; n4 < 4; n4++) {
                uint32_t addr = kvb + ((n4 * 16 + ldr) * FSTR + d * 16 + ldc) * 2;
                uint32_t kb0[4], kb1[4];
                LDMX4(kb0, addr);              // Khi
                LDMX4(kb1, addr + FTILE * 2);  // Klo
                MMA_BF16(Sf[2 * n4],     qh[d], kb0[0], kb0[2]);
                MMA_BF16(Sf[2 * n4 + 1], qh[d], kb0[1], kb0[3]);
                MMA_BF16(Sf[2 * n4],     qh[d], kb1[0], kb1[2]);
                MMA_BF16(Sf[2 * n4 + 1], qh[d], kb1[1], kb1[3]);
                MMA_BF16(Sf[2 * n4],     ql[d], kb0[0], kb0[2]);
                MMA_BF16(Sf[2 * n4 + 1], ql[d], kb0[1], kb0[3]);
            }
        }

        // ---- causal mask (only the top two k-tiles can cross the diagonal)
        const int r0 = q0 + wrow + grp;
        if (kt >= 2 * qt) {
#pragma unroll
            for (int nb = 0; nb < 8; nb++) {
#pragma unroll
                for (int j = 0; j < 2; j++) {
                    int key = kt * 64 + nb * 8 + qq + j;
                    if (key > r0)     Sf[nb][j]     = -1e30f;
                    if (key > r0 + 8) Sf[nb][2 + j] = -1e30f;
                }
            }
        }

        // ---- online softmax (rows grp, grp+8)
        float mx0 = -1e30f, mx1 = -1e30f;
#pragma unroll
        for (int nb = 0; nb < 8; nb++) {
            mx0 = fmaxf(mx0, fmaxf(Sf[nb][0], Sf[nb][1]));
            mx1 = fmaxf(mx1, fmaxf(Sf[nb][2], Sf[nb][3]));
        }
        mx0 = fmaxf(mx0, __shfl_xor_sync(0xffffffff, mx0, 1));
        mx0 = fmaxf(mx0, __shfl_xor_sync(0xffffffff, mx0, 2));
        mx1 = fmaxf(mx1, __shfl_xor_sync(0xffffffff, mx1, 1));
        mx1 = fmaxf(mx1, __shfl_xor_sync(0xffffffff, mx1, 2));
        float mn0 = fmaxf(m0, mx0), mn1 = fmaxf(m1, mx1);
        float a0 = __expf(m0 - mn0), a1 = __expf(m1 - mn1);
        float s0 = 0.f, s1 = 0.f;
#pragma unroll
        for (int nb = 0; nb < 8; nb++) {
            Sf[nb][0] = __expf(Sf[nb][0] - mn0); s0 += Sf[nb][0];
            Sf[nb][1] = __expf(Sf[nb][1] - mn0); s0 += Sf[nb][1];
            Sf[nb][2] = __expf(Sf[nb][2] - mn1); s1 += Sf[nb][2];
            Sf[nb][3] = __expf(Sf[nb][3] - mn1); s1 += Sf[nb][3];
        }
        s0 += __shfl_xor_sync(0xffffffff, s0, 1);
        s0 += __shfl_xor_sync(0xffffffff, s0, 2);
        s1 += __shfl_xor_sync(0xffffffff, s1, 1);
        s1 += __shfl_xor_sync(0xffffffff, s1, 2);
        l0 = l0 * a0 + s0;  l1 = l1 * a1 + s1;
        m0 = mn0;           m1 = mn1;
#pragma unroll
        for (int nb = 0; nb < 16; nb++) {
            Of[nb][0] *= a0; Of[nb][1] *= a0;
            Of[nb][2] *= a1; Of[nb][3] *= a1;
        }

        // ---- O += P V  (P packed from Sf on the fly)
        const uint32_t vb = kvb + 2 * FTILE * 2;
#pragma unroll
        for (int j = 0; j < 4; j++) {          // 16-key steps
            uint32_t ph[4], pl[4];
            split_pack(Sf[2 * j][0],     Sf[2 * j][1],     ph[0], pl[0]);
            split_pack(Sf[2 * j][2],     Sf[2 * j][3],     ph[1], pl[1]);
            split_pack(Sf[2 * j + 1][0], Sf[2 * j + 1][1], ph[2], pl[2]);
            split_pack(Sf[2 * j + 1][2], Sf[2 * j + 1][3], ph[3], pl[3]);
#pragma unroll
            for (int nb2 = 0; nb2 < 8; nb2++) {  // 16-dim groups
                uint32_t addr = vb + ((j * 16 + ldr) * FSTR + nb2 * 16 + ldc) * 2;
                uint32_t vh[4], vl[4];
                LDMX4T(vh, addr);
                LDMX4T(vl, addr + FTILE * 2);
                MMA_BF16(Of[2 * nb2],     ph, vh[0], vh[1]);
                MMA_BF16(Of[2 * nb2 + 1], ph, vh[2], vh[3]);
                MMA_BF16(Of[2 * nb2],     ph, vl[0], vl[1]);
                MMA_BF16(Of[2 * nb2 + 1], ph, vl[2], vl[3]);
                MMA_BF16(Of[2 * nb2],     pl, vh[0], vh[1]);
                MMA_BF16(Of[2 * nb2 + 1], pl, vh[2], vh[3]);
            }
        }

        __syncthreads();
        if (kt + 2 <= ktmax) load_kv(kt + 2, kt & 1);
    }

    // ---- epilogue: normalize, split to bf16 hi/lo, write GEMM2 operand
    const int b = bh >> 4, h = bh & 15;
    const float inv0 = 1.0f / l0, inv1 = 1.0f / l1;
    const size_t row0 = (size_t)(b * SSQ + q0 + wrow + grp) * DDIM + (h << 7);
    const size_t row1 = row0 + (size_t)8 * DDIM;
#pragma unroll
    for (int nb = 0; nb < 16; nb++) {
        uint32_t hi, lo;
        size_t o = row0 + nb * 8 + qq;
        split_pack(Of[nb][0] * inv0, Of[nb][1] * inv0, hi, lo);
        *(uint32_t*)(ohi + o) = hi;  *(uint32_t*)(olo + o) = lo;
        o = row1 + nb * 8 + qq;
        split_pack(Of[nb][2] * inv1, Of[nb][3] * inv1, hi, lo);
        *(uint32_t*)(ohi + o) = hi;  *(uint32_t*)(olo + o) = lo;
    }
}

// ---------------------------------------------------------------------------
// Launch
// ---------------------------------------------------------------------------
extern "C" void kernel_launch(void* const* d_in, const int* in_sizes, int n_in,
                              void* d_out, int out_size)
{
    const float* x     = (const float*)d_in[0];
    const float* wqkv  = (const float*)d_in[1];
    const float* wout  = (const float*)d_in[2];
    const float* fcos  = (const float*)d_in[3];
    const float* fsin  = (const float*)d_in[4];
    float* out = (float*)d_out;

    float* qkv_p = nullptr;
    __nv_bfloat16 *xhi, *xlo, *whi, *wlo, *ahi, *alo, *uhi, *ulo;
    __nv_bfloat16 *qh, *ql, *kh, *kl, *vh, *vl;
    cudaGetSymbolAddress((void**)&qkv_p, g_qkv);
    cudaGetSymbolAddress((void**)&xhi, g_xhi);
    cudaGetSymbolAddress((void**)&xlo, g_xlo);
    cudaGetSymbolAddress((void**)&whi, g_whi);
    cudaGetSymbolAddress((void**)&wlo, g_wlo);
    cudaGetSymbolAddress((void**)&ahi, g_ahi);
    cudaGetSymbolAddress((void**)&alo, g_alo);
    cudaGetSymbolAddress((void**)&uhi, g_uhi);
    cudaGetSymbolAddress((void**)&ulo, g_ulo);
    cudaGetSymbolAddress((void**)&qh, g_qhi);
    cudaGetSymbolAddress((void**)&ql, g_qlo);
    cudaGetSymbolAddress((void**)&kh, g_khi);
    cudaGetSymbolAddress((void**)&kl, g_klo);
    cudaGetSymbolAddress((void**)&vh, g_vhi);
    cudaGetSymbolAddress((void**)&vl, g_vlo);

    cudaFuncSetAttribute(mma_gemm, cudaFuncAttributeMaxDynamicSharedMemorySize,
                         GEMM_SMEM);
    cudaFuncSetAttribute(flash_mma, cudaFuncAttributeMaxDynamicSharedMemorySize,
                         FLASH_SMEM);

    // operand splits
    split_bf16<<<(M1 * DDIM / 4) / 256, 256>>>(x, xhi, xlo, M1 * DDIM / 4);
    split_bf16<<<(N1 * DDIM / 4) / 256, 256>>>(wqkv, whi, wlo, N1 * DDIM / 4);
    split_bf16<<<(DDIM * DDIM / 4) / 256, 256>>>(wout, uhi, ulo, DDIM * DDIM / 4);

    // 1) QKV projection (mma.sync)
    mma_gemm<<<dim3(N1 / 128, M1 / 128), 256, GEMM_SMEM>>>(
        xhi, xlo, whi, wlo, qkv_p, N1, DDIM);

    // 2) RoPE + relayout + split
    rope_split_kernel<<<(M1 * HH * 64) / 256, 256>>>(fcos, fsin);

    // 3) Flash attention (mma.sync) -> writes g_ahi/g_alo directly
    flash_mma<<<dim3(SSQ / 128, FB), 256, FLASH_SMEM>>>(
        qh, ql, kh, kl, vh, vl, ahi, alo);

    // 4) Output projection (mma.sync)
    mma_gemm<<<dim3(DDIM / 128, M1 / 128), 256, GEMM_SMEM>>>(
        ahi, alo, uhi, ulo, out, DDIM, DDIM);
}

// round 5
// speedup vs baseline: 3.4096x; 1.0206x over previous
#include <cuda_runtime.h>
#include <cuda_bf16.h>
#include <cstdint>

// Problem constants
#define BB 2
#define SSQ 2048
#define DDIM 2048
#define HH 16
#define M1 (BB * SSQ)      // 4096
#define N1 (3 * DDIM)      // 6144
#define FB (BB * HH)       // 32 (b,h) pairs

// ---------------------------------------------------------------------------
// Scratch (__device__ globals: allocation-free rule)
// ---------------------------------------------------------------------------
__device__ __nv_bfloat16 g_xhi[(size_t)M1 * DDIM];
__device__ __nv_bfloat16 g_xlo[(size_t)M1 * DDIM];
__device__ __nv_bfloat16 g_whi[(size_t)N1 * DDIM];
__device__ __nv_bfloat16 g_wlo[(size_t)N1 * DDIM];
__device__ __nv_bfloat16 g_ahi[(size_t)M1 * DDIM];
__device__ __nv_bfloat16 g_alo[(size_t)M1 * DDIM];
__device__ __nv_bfloat16 g_uhi[(size_t)DDIM * DDIM];
__device__ __nv_bfloat16 g_ulo[(size_t)DDIM * DDIM];
// flash operands, layout [bh][s][128], bf16 hi/lo
__device__ __nv_bfloat16 g_qhi[(size_t)FB * SSQ * 128];
__device__ __nv_bfloat16 g_qlo[(size_t)FB * SSQ * 128];
__device__ __nv_bfloat16 g_khi[(size_t)FB * SSQ * 128];
__device__ __nv_bfloat16 g_klo[(size_t)FB * SSQ * 128];
__device__ __nv_bfloat16 g_vhi[(size_t)FB * SSQ * 128];
__device__ __nv_bfloat16 g_vlo[(size_t)FB * SSQ * 128];

__device__ __forceinline__ uint32_t smem_u32(const void* p) {
    uint32_t a;
    asm("{ .reg .u64 t; cvta.to.shared.u64 t, %1; cvt.u32.u64 %0, t; }"
        : "=r"(a) : "l"(p));
    return a;
}

#define LDMX4(R, A) \
    asm volatile("ldmatrix.sync.aligned.m8n8.x4.shared.b16 {%0,%1,%2,%3}, [%4];" \
        : "=r"((R)[0]), "=r"((R)[1]), "=r"((R)[2]), "=r"((R)[3]) : "r"(A))
#define LDMX4T(R, A) \
    asm volatile("ldmatrix.sync.aligned.m8n8.x4.trans.shared.b16 {%0,%1,%2,%3}, [%4];" \
        : "=r"((R)[0]), "=r"((R)[1]), "=r"((R)[2]), "=r"((R)[3]) : "r"(A))

#define MMA_BF16(ac, a, b0v, b1v) \
    asm volatile("mma.sync.aligned.m16n8k16.row.col.f32.bf16.bf16.f32 " \
        "{%0,%1,%2,%3},{%4,%5,%6,%7},{%8,%9},{%0,%1,%2,%3};" \
        : "+f"((ac)[0]), "+f"((ac)[1]), "+f"((ac)[2]), "+f"((ac)[3]) \
        : "r"((a)[0]), "r"((a)[1]), "r"((a)[2]), "r"((a)[3]), \
          "r"(b0v), "r"(b1v))

#define CP_ASYNC16(s, g) \
    asm volatile("cp.async.cg.shared.global [%0], [%1], 16;" :: "r"(s), "l"(g))
#define CP_COMMIT() asm volatile("cp.async.commit_group;" ::: "memory")
#define CP_WAIT1()  asm volatile("cp.async.wait_group 1;" ::: "memory")
#define CP_WAIT0()  asm volatile("cp.async.wait_group 0;" ::: "memory")

// split fp32 pair -> packed bf16x2 (hi) + packed bf16x2 (lo residual)
__device__ __forceinline__ void split_pack(float x, float y,
                                           uint32_t& hi, uint32_t& lo) {
    __nv_bfloat162 h = __floats2bfloat162_rn(x, y);
    hi = *reinterpret_cast<uint32_t*>(&h);
    __nv_bfloat162 l = __floats2bfloat162_rn(x - __low2float(h),
                                             y - __high2float(h));
    lo = *reinterpret_cast<uint32_t*>(&l);
}

__device__ __forceinline__ void split_write(__nv_bfloat16* hi_arr,
                                            __nv_bfloat16* lo_arr,
                                            size_t o, float x, float y) {
    uint32_t hi, lo;
    split_pack(x, y, hi, lo);
    *(uint32_t*)(hi_arr + o) = hi;
    *(uint32_t*)(lo_arr + o) = lo;
}

// ---------------------------------------------------------------------------
// fp32 -> (bf16 hi, bf16 lo) split (for GEMM operands)
// ---------------------------------------------------------------------------
__global__ __launch_bounds__(256) void split_bf16(
    const float* __restrict__ src, __nv_bfloat16* __restrict__ hi,
    __nv_bfloat16* __restrict__ lo, int n4)
{
    int i = blockIdx.x * blockDim.x + threadIdx.x;
    if (i >= n4) return;
    float4 v = ((const float4*)src)[i];
    uint32_t h0, l0, h1, l1;
    split_pack(v.x, v.y, h0, l0);
    split_pack(v.z, v.w, h1, l1);
    ((uint32_t*)hi)[i * 2 + 0] = h0;
    ((uint32_t*)hi)[i * 2 + 1] = h1;
    ((uint32_t*)lo)[i * 2 + 0] = l0;
    ((uint32_t*)lo)[i * 2 + 1] = l1;
}

// ---------------------------------------------------------------------------
// mma.sync GEMM, templated epilogue:
//  MODE 0: plain fp32 store to C
//  MODE 1: fused RoPE + relayout + bf16 split into g_q/k/v hi/lo (QKV GEMM)
// CTA 128x128, warp 64x32, K-chunk 32, cp.async double buffering, 2 CTAs/SM.
// ---------------------------------------------------------------------------
#define KC 32
#define AST 40
#define TILE_E (128 * AST)
#define STAGE_E (4 * TILE_E)
#define GEMM_SMEM (2 * STAGE_E * 2)

template <int MODE>
__global__ __launch_bounds__(256, 2) void mma_gemm_t(
    const __nv_bfloat16* __restrict__ Ahi, const __nv_bfloat16* __restrict__ Alo,
    const __nv_bfloat16* __restrict__ Bhi, const __nv_bfloat16* __restrict__ Blo,
    float* __restrict__ C, int Ntot, int K,
    const float* __restrict__ fc, const float* __restrict__ fs)
{
    extern __shared__ __nv_bfloat16 smb[];
    const uint32_t sbase = smem_u32(smb);
    const int t = threadIdx.x;
    const int lane = t & 31, warp = t >> 5;
    const int bm = blockIdx.y << 7, bn = blockIdx.x << 7;
    const int wm = (warp >> 2) << 6;
    const int wn = (warp & 3) << 5;

    const int lr = t >> 1;
    const int lc0 = (t & 1) << 1;

    const __nv_bfloat16* gsrc[4] = {
        Ahi + (size_t)(bm + lr) * K, Alo + (size_t)(bm + lr) * K,
        Bhi + (size_t)(bn + lr) * K, Blo + (size_t)(bn + lr) * K };

    auto load_stage = [&](int kc, int buf) {
        uint32_t sb = sbase + buf * STAGE_E * 2;
#pragma unroll
        for (int tile = 0; tile < 4; tile++) {
#pragma unroll
            for (int i = 0; i < 2; i++) {
                int c = lc0 + i;
                uint32_t sa = sb + tile * TILE_E * 2 + (lr * AST + c * 8) * 2;
                const void* ga = gsrc[tile] + kc * KC + c * 8;
                CP_ASYNC16(sa, ga);
            }
        }
        CP_COMMIT();
    };

    float acc[4][4][4] = {};
    const int NIT = K / KC;

    load_stage(0, 0);

    const int ldrow = lane & 15;
    const int ldcol = (lane >> 4) << 3;

    for (int it = 0; it < NIT; it++) {
        if (it + 1 < NIT) { load_stage(it + 1, (it + 1) & 1); CP_WAIT1(); }
        else              { CP_WAIT0(); }
        __syncthreads();

        const uint32_t sb = sbase + (it & 1) * STAGE_E * 2;
#pragma unroll
        for (int kh = 0; kh < 2; kh++) {
            uint32_t aH[4][4], aL[4][4], bH[4][2], bL[4][2];
            const int colb = (kh * 16 + ldcol) * 2;
#pragma unroll
            for (int mt = 0; mt < 4; mt++) {
                uint32_t ra = sb + (wm + mt * 16 + ldrow) * (AST * 2) + colb;
                LDMX4(aH[mt], ra);
                LDMX4(aL[mt], ra + TILE_E * 2);
            }
#pragma unroll
            for (int n2 = 0; n2 < 2; n2++) {
                uint32_t rb = sb + 2 * TILE_E * 2 +
                              (wn + n2 * 16 + ldrow) * (AST * 2) + colb;
                uint32_t r[4];
                LDMX4(r, rb);
                bH[n2 * 2 + 0][0] = r[0]; bH[n2 * 2 + 0][1] = r[2];
                bH[n2 * 2 + 1][0] = r[1]; bH[n2 * 2 + 1][1] = r[3];
                LDMX4(r, rb + TILE_E * 2);
                bL[n2 * 2 + 0][0] = r[0]; bL[n2 * 2 + 0][1] = r[2];
                bL[n2 * 2 + 1][0] = r[1]; bL[n2 * 2 + 1][1] = r[3];
            }
#pragma unroll
            for (int mt = 0; mt < 4; mt++) {
#pragma unroll
                for (int nt = 0; nt < 4; nt++) {
                    MMA_BF16(acc[mt][nt], aH[mt], bH[nt][0], bH[nt][1]);
                    MMA_BF16(acc[mt][nt], aH[mt], bL[nt][0], bL[nt][1]);
                    MMA_BF16(acc[mt][nt], aL[mt], bH[nt][0], bH[nt][1]);
                }
            }
        }
        __syncthreads();
    }

    const int grp = lane >> 2, qq = (lane & 3) << 1;

    if (MODE == 0) {
#pragma unroll
        for (int mt = 0; mt < 4; mt++) {
#pragma unroll
            for (int nt = 0; nt < 4; nt++) {
                float* p = C + (size_t)(bm + wm + mt * 16 + grp) * Ntot
                             + bn + wn + nt * 8 + qq;
                p[0] = acc[mt][nt][0];
                p[1] = acc[mt][nt][1];
                float* p2 = p + (size_t)8 * Ntot;
                p2[0] = acc[mt][nt][2];
                p2[1] = acc[mt][nt][3];
            }
        }
    } else {
        // fused RoPE + relayout + split; CTA-uniform region (q/k/v)
        const int region = bn >> 11;            // 0=q, 1=k, 2=v
        const float scale = 0.08838834764831845f; // 1/sqrt(128)
#pragma unroll
        for (int mt = 0; mt < 4; mt++) {
            const int r0 = bm + wm + mt * 16 + grp;
            const int b  = r0 >> 11;
            const int s0 = r0 & (SSQ - 1);
            const int s1 = s0 + 8;              // same b (128-row blocks)
#pragma unroll
            for (int nt = 0; nt < 4; nt++) {
                const int c  = bn + wn + nt * 8 + qq;
                const int cr = c & (DDIM - 1);
                const int h  = cr >> 7;
                const int ch = cr & 127;
                const int i  = ch >> 1;
                const size_t ob = ((size_t)(b * HH + h) * SSQ);
                const size_t o0 = (ob + s0) * 128 + ch;
                const size_t o1 = (ob + s1) * 128 + ch;
                float x0 = acc[mt][nt][0], y0 = acc[mt][nt][1];
                float x1 = acc[mt][nt][2], y1 = acc[mt][nt][3];
                if (region == 2) {
                    split_write(g_vhi, g_vlo, o0, x0, y0);
                    split_write(g_vhi, g_vlo, o1, x1, y1);
                } else {
                    float c0 = fc[(s0 << 6) + i], sn0 = fs[(s0 << 6) + i];
                    float c1 = fc[(s1 << 6) + i], sn1 = fs[(s1 << 6) + i];
                    float rx0 = x0 * c0 - y0 * sn0, ry0 = x0 * sn0 + y0 * c0;
                    float rx1 = x1 * c1 - y1 * sn1, ry1 = x1 * sn1 + y1 * c1;
                    if (region == 0) {
                        split_write(g_qhi, g_qlo, o0, rx0 * scale, ry0 * scale);
                        split_write(g_qhi, g_qlo, o1, rx1 * scale, ry1 * scale);
                    } else {
                        split_write(g_khi, g_klo, o0, rx0, ry0);
                        split_write(g_khi, g_klo, o1, rx1, ry1);
                    }
                }
            }
        }
    }
}

// ---------------------------------------------------------------------------
// Flash attention on mma.sync (bf16 3-term split, fp32 softmax).
// ---------------------------------------------------------------------------
#define FSTR 136
#define FTILE (64 * FSTR)
#define QTILE (128 * FSTR)
#define FLASH_SMEM ((2 * QTILE + 8 * FTILE) * 2)   // 208896 bytes

__global__ __launch_bounds__(256, 1) void flash_mma(
    const __nv_bfloat16* __restrict__ qhi, const __nv_bfloat16* __restrict__ qlo,
    const __nv_bfloat16* __restrict__ khi, const __nv_bfloat16* __restrict__ klo,
    const __nv_bfloat16* __restrict__ vhi, const __nv_bfloat16* __restrict__ vlo,
    __nv_bfloat16* __restrict__ ohi, __nv_bfloat16* __restrict__ olo)
{
    extern __shared__ __nv_bfloat16 fsm[];
    const uint32_t sb = smem_u32(fsm);
    const int t = threadIdx.x;
    const int lane = t & 31, warp = t >> 5;
    const int qt = (int)gridDim.x - 1 - (int)blockIdx.x;
    const int bh = blockIdx.y;
    const int q0 = qt << 7;
    const size_t bhbase = (size_t)bh * SSQ * 128;

    const int ldr = lane & 15;
    const int ldc = (lane >> 4) << 3;
    const int grp = lane >> 2;
    const int qq  = (lane & 3) << 1;

    {
        int r = t >> 1;
        int e0 = (t & 1) << 6;
        const __nv_bfloat16* srcs[2] = {
            qhi + bhbase + (size_t)(q0 + r) * 128 + e0,
            qlo + bhbase + (size_t)(q0 + r) * 128 + e0 };
        uint32_t s0 = sb + (r * FSTR + e0) * 2;
#pragma unroll
        for (int tile = 0; tile < 2; tile++)
#pragma unroll
            for (int c = 0; c < 8; c++)
                CP_ASYNC16(s0 + tile * QTILE * 2 + c * 16, srcs[tile] + c * 8);
        CP_COMMIT();
    }

    auto load_kv = [&](int kt, int buf) {
        int r = t >> 2;
        int e0 = (t & 3) << 5;
        size_t g0 = bhbase + (size_t)(kt * 64 + r) * 128 + e0;
        const __nv_bfloat16* srcs[4] = { khi + g0, klo + g0, vhi + g0, vlo + g0 };
        uint32_t s0 = sb + (2 * QTILE + buf * 4 * FTILE + r * FSTR + e0) * 2;
#pragma unroll
        for (int tile = 0; tile < 4; tile++)
#pragma unroll
            for (int c = 0; c < 4; c++)
                CP_ASYNC16(s0 + tile * FTILE * 2 + c * 16, srcs[tile] + c * 8);
        CP_COMMIT();
    };

    CP_WAIT0();
    __syncthreads();
    uint32_t qh[8][4], ql[8][4];
    const int wrow = warp << 4;
#pragma unroll
    for (int d = 0; d < 8; d++) {
        uint32_t a = sb + ((wrow + ldr) * FSTR + d * 16 + ldc) * 2;
        LDMX4(qh[d], a);
        LDMX4(ql[d], a + QTILE * 2);
    }

    const int ktmax = 2 * qt + 1;
    load_kv(0, 0);
    load_kv(1, 1);

    float Of[16][4] = {};
    float m0 = -1e30f, m1 = -1e30f, l0 = 0.f, l1 = 0.f;

    for (int kt = 0; kt <= ktmax; kt++) {
        if (kt == ktmax) { CP_WAIT0(); } else { CP_WAIT1(); }
        __syncthreads();

        const uint32_t kvb = sb + (2 * QTILE + (kt & 1) * 4 * FTILE) * 2;

        float Sf[8][4] = {};
#pragma unroll
        for (int d = 0; d < 8; d++) {
#pragma unroll
            for (int n4 = 0; n4 < 4; n4++) {
                uint32_t addr = kvb + ((n4 * 16 + ldr) * FSTR + d * 16 + ldc) * 2;
                uint32_t kb0[4], kb1[4];
                LDMX4(kb0, addr);
                LDMX4(kb1, addr + FTILE * 2);
                MMA_BF16(Sf[2 * n4],     qh[d], kb0[0], kb0[2]);
                MMA_BF16(Sf[2 * n4 + 1], qh[d], kb0[1], kb0[3]);
                MMA_BF16(Sf[2 * n4],     qh[d], kb1[0], kb1[2]);
                MMA_BF16(Sf[2 * n4 + 1], qh[d], kb1[1], kb1[3]);
                MMA_BF16(Sf[2 * n4],     ql[d], kb0[0], kb0[2]);
                MMA_BF16(Sf[2 * n4 + 1], ql[d], kb0[1], kb0[3]);
            }
        }

        const int r0 = q0 + wrow + grp;
        if (kt >= 2 * qt) {
#pragma unroll
            for (int nb = 0; nb < 8; nb++) {
#pragma unroll
                for (int j = 0; j < 2; j++) {
                    int key = kt * 64 + nb * 8 + qq + j;
                    if (key > r0)     Sf[nb][j]     = -1e30f;
                    if (key > r0 + 8) Sf[nb][2 + j] = -1e30f;
                }
            }
        }

        float mx0 = -1e30f, mx1 = -1e30f;
#pragma unroll
        for (int nb = 0; nb < 8; nb++) {
            mx0 = fmaxf(mx0, fmaxf(Sf[nb][0], Sf[nb][1]));
            mx1 = fmaxf(mx1, fmaxf(Sf[nb][2], Sf[nb][3]));
        }
        mx0 = fmaxf(mx0, __shfl_xor_sync(0xffffffff, mx0, 1));
        mx0 = fmaxf(mx0, __shfl_xor_sync(0xffffffff, mx0, 2));
        mx1 = fmaxf(mx1, __shfl_xor_sync(0xffffffff, mx1, 1));
        mx1 = fmaxf(mx1, __shfl_xor_sync(0xffffffff, mx1, 2));
        float mn0 = fmaxf(m0, mx0), mn1 = fmaxf(m1, mx1);
        float a0 = __expf(m0 - mn0), a1 = __expf(m1 - mn1);
        float s0 = 0.f, s1 = 0.f;
#pragma unroll
        for (int nb = 0; nb < 8; nb++) {
            Sf[nb][0] = __expf(Sf[nb][0] - mn0); s0 += Sf[nb][0];
            Sf[nb][1] = __expf(Sf[nb][1] - mn0); s0 += Sf[nb][1];
            Sf[nb][2] = __expf(Sf[nb][2] - mn1); s1 += Sf[nb][2];
            Sf[nb][3] = __expf(Sf[nb][3] - mn1); s1 += Sf[nb][3];
        }
        s0 += __shfl_xor_sync(0xffffffff, s0, 1);
        s0 += __shfl_xor_sync(0xffffffff, s0, 2);
        s1 += __shfl_xor_sync(0xffffffff, s1, 1);
        s1 += __shfl_xor_sync(0xffffffff, s1, 2);
        l0 = l0 * a0 + s0;  l1 = l1 * a1 + s1;
        m0 = mn0;           m1 = mn1;
#pragma unroll
        for (int nb = 0; nb < 16; nb++) {
            Of[nb][0] *= a0; Of[nb][1] *= a0;
            Of[nb][2] *= a1; Of[nb][3] *= a1;
        }

        const uint32_t vb = kvb + 2 * FTILE * 2;
#pragma unroll
        for (int j = 0; j < 4; j++) {
            uint32_t ph[4], pl[4];
            split_pack(Sf[2 * j][0],     Sf[2 * j][1],     ph[0], pl[0]);
            split_pack(Sf[2 * j][2],     Sf[2 * j][3],     ph[1], pl[1]);
            split_pack(Sf[2 * j + 1][0], Sf[2 * j + 1][1], ph[2], pl[2]);
            split_pack(Sf[2 * j + 1][2], Sf[2 * j + 1][3], ph[3], pl[3]);
#pragma unroll
            for (int nb2 = 0; nb2 < 8; nb2++) {
                uint32_t addr = vb + ((j * 16 + ldr) * FSTR + nb2 * 16 + ldc) * 2;
                uint32_t vh[4], vl[4];
                LDMX4T(vh, addr);
                LDMX4T(vl, addr + FTILE * 2);
                MMA_BF16(Of[2 * nb2],     ph, vh[0], vh[1]);
                MMA_BF16(Of[2 * nb2 + 1], ph, vh[2], vh[3]);
                MMA_BF16(Of[2 * nb2],     ph, vl[0], vl[1]);
                MMA_BF16(Of[2 * nb2 + 1], ph, vl[2], vl[3]);
                MMA_BF16(Of[2 * nb2],     pl, vh[0], vh[1]);
                MMA_BF16(Of[2 * nb2 + 1], pl, vh[2], vh[3]);
            }
        }

        __syncthreads();
        if (kt + 2 <= ktmax) load_kv(kt + 2, kt & 1);
    }

    const int b = bh >> 4, h = bh & 15;
    const float inv0 = 1.0f / l0, inv1 = 1.0f / l1;
    const size_t row0 = (size_t)(b * SSQ + q0 + wrow + grp) * DDIM + (h << 7);
    const size_t row1 = row0 + (size_t)8 * DDIM;
#pragma unroll
    for (int nb = 0; nb < 16; nb++) {
        size_t o = row0 + nb * 8 + qq;
        split_write(ohi, olo, o, Of[nb][0] * inv0, Of[nb][1] * inv0);
        o = row1 + nb * 8 + qq;
        split_write(ohi, olo, o, Of[nb][2] * inv1, Of[nb][3] * inv1);
    }
}

// ---------------------------------------------------------------------------
// Launch
// ---------------------------------------------------------------------------
extern "C" void kernel_launch(void* const* d_in, const int* in_sizes, int n_in,
                              void* d_out, int out_size)
{
    const float* x     = (const float*)d_in[0];
    const float* wqkv  = (const float*)d_in[1];
    const float* wout  = (const float*)d_in[2];
    const float* fcos  = (const float*)d_in[3];
    const float* fsin  = (const float*)d_in[4];
    float* out = (float*)d_out;

    __nv_bfloat16 *xhi, *xlo, *whi, *wlo, *ahi, *alo, *uhi, *ulo;
    __nv_bfloat16 *qh, *ql, *kh, *kl, *vh, *vl;
    cudaGetSymbolAddress((void**)&xhi, g_xhi);
    cudaGetSymbolAddress((void**)&xlo, g_xlo);
    cudaGetSymbolAddress((void**)&whi, g_whi);
    cudaGetSymbolAddress((void**)&wlo, g_wlo);
    cudaGetSymbolAddress((void**)&ahi, g_ahi);
    cudaGetSymbolAddress((void**)&alo, g_alo);
    cudaGetSymbolAddress((void**)&uhi, g_uhi);
    cudaGetSymbolAddress((void**)&ulo, g_ulo);
    cudaGetSymbolAddress((void**)&qh, g_qhi);
    cudaGetSymbolAddress((void**)&ql, g_qlo);
    cudaGetSymbolAddress((void**)&kh, g_khi);
    cudaGetSymbolAddress((void**)&kl, g_klo);
    cudaGetSymbolAddress((void**)&vh, g_vhi);
    cudaGetSymbolAddress((void**)&vl, g_vlo);

    cudaFuncSetAttribute(mma_gemm_t<0>,
                         cudaFuncAttributeMaxDynamicSharedMemorySize, GEMM_SMEM);
    cudaFuncSetAttribute(mma_gemm_t<1>,
                         cudaFuncAttributeMaxDynamicSharedMemorySize, GEMM_SMEM);
    cudaFuncSetAttribute(flash_mma,
                         cudaFuncAttributeMaxDynamicSharedMemorySize, FLASH_SMEM);

    // operand splits
    split_bf16<<<(M1 * DDIM / 4) / 256, 256>>>(x, xhi, xlo, M1 * DDIM / 4);
    split_bf16<<<(N1 * DDIM / 4) / 256, 256>>>(wqkv, whi, wlo, N1 * DDIM / 4);
    split_bf16<<<(DDIM * DDIM / 4) / 256, 256>>>(wout, uhi, ulo, DDIM * DDIM / 4);

    // 1) QKV projection with fused RoPE + split epilogue
    mma_gemm_t<1><<<dim3(N1 / 128, M1 / 128), 256, GEMM_SMEM>>>(
        xhi, xlo, whi, wlo, nullptr, N1, DDIM, fcos, fsin);

    // 2) Flash attention (mma.sync) -> writes g_ahi/g_alo directly
    flash_mma<<<dim3(SSQ / 128, FB), 256, FLASH_SMEM>>>(
        qh, ql, kh, kl, vh, vl, ahi, alo);

    // 3) Output projection
    mma_gemm_t<0><<<dim3(DDIM / 128, M1 / 128), 256, GEMM_SMEM>>>(
        ahi, alo, uhi, ulo, out, DDIM, DDIM, nullptr, nullptr);
}